// round 2
// baseline (speedup 1.0000x reference)
#include <cuda_runtime.h>
#include <cuda_bf16.h>

// Problem constants
#define BATCH   2
#define AGENT   6
#define XW      8
#define YW      8
#define WIN     7
#define DIM     256
#define HEADS   8
#define DH      32
#define NWIN    (BATCH * XW * YW)      // 128 windows
#define NTOK    (AGENT * WIN * WIN)    // 294 tokens per window
#define MROWS   (NWIN * NTOK)          // 37632
#define NBIAS   1859                   // (2*6-1)*(13)*(13)

#define KPAD 36                        // K/V smem row pad (16B-aligned rows, conflict-free)
#define PROW_PAD 296                   // per-warp P row pad: 296 floats = 1184 B (16B aligned)

__device__ int   g_rowbase[MROWS];
__device__ float g_qkv[(size_t)MROWS * 3 * DIM];   // ~115.6 MB
__device__ float g_att[(size_t)MROWS * DIM];       // ~38.5 MB

// ---------------------------------------------------------------------------
// rowbase: maps GEMM row m=(window w, token t) to element offset in x / out
// x layout (B, L, X, Y, W1, W2, C); out layout identical.
// ---------------------------------------------------------------------------
__global__ void rowbase_kernel(int* __restrict__ rb) {
    int m = blockIdx.x * 256 + threadIdx.x;
    if (m >= MROWS) return;
    int w = m / NTOK, t = m % NTOK;
    int b = w >> 6, xy = w & 63, x_ = xy >> 3, y_ = xy & 7;
    int l = t / 49, r = t % 49, w1 = r / 7, w2 = r % 7;
    rb[m] = ((((((b * AGENT + l) * XW + x_) * YW + y_) * WIN + w1) * WIN + w2)) * DIM;
}

// ---------------------------------------------------------------------------
// Tiled fp32 GEMM: C[m][n] = sum_k A[m][k] * W[n][k]   (K = 256 fixed)
// gatherA: A row m starts at A + rowbase[m]  (else m*256 contiguous)
// scatterOut: C row m starts at Cout + rowbase[m] (requires N<=256), else m*N
// BM=BN=64, BK=16, 256 threads, 4x4 microtile.
// ---------------------------------------------------------------------------
template <int GATHER_A, int SCATTER_OUT>
__global__ void __launch_bounds__(256)
gemm_kernel(const float* __restrict__ A, const int* __restrict__ rowbase,
            const float* __restrict__ W, float* __restrict__ C, int N) {
    __shared__ float As[16][65];
    __shared__ float Bs[16][65];

    int tid = threadIdx.x;
    int bm = blockIdx.y * 64;
    int bn = blockIdx.x * 64;

    int lr = tid >> 2;          // 0..63  (row within tile)
    int lk = (tid & 3) * 4;     // 0,4,8,12

    int m_load = bm + lr;
    long abase = GATHER_A ? (long)rowbase[m_load] : (long)m_load * DIM;
    const float* aptr = A + abase;
    const float* bptr = W + (long)(bn + lr) * DIM;

    int tx = tid & 15, ty = tid >> 4;
    float acc[4][4];
#pragma unroll
    for (int i = 0; i < 4; i++)
#pragma unroll
        for (int j = 0; j < 4; j++) acc[i][j] = 0.f;

    for (int k0 = 0; k0 < DIM; k0 += 16) {
        float4 av = *(const float4*)(aptr + k0 + lk);
        float4 bv = *(const float4*)(bptr + k0 + lk);
        As[lk + 0][lr] = av.x; As[lk + 1][lr] = av.y;
        As[lk + 2][lr] = av.z; As[lk + 3][lr] = av.w;
        Bs[lk + 0][lr] = bv.x; Bs[lk + 1][lr] = bv.y;
        Bs[lk + 2][lr] = bv.z; Bs[lk + 3][lr] = bv.w;
        __syncthreads();
#pragma unroll
        for (int k = 0; k < 16; k++) {
            float a0 = As[k][ty * 4 + 0], a1 = As[k][ty * 4 + 1];
            float a2 = As[k][ty * 4 + 2], a3 = As[k][ty * 4 + 3];
            float b0 = Bs[k][tx * 4 + 0], b1 = Bs[k][tx * 4 + 1];
            float b2 = Bs[k][tx * 4 + 2], b3 = Bs[k][tx * 4 + 3];
            acc[0][0] = fmaf(a0, b0, acc[0][0]); acc[0][1] = fmaf(a0, b1, acc[0][1]);
            acc[0][2] = fmaf(a0, b2, acc[0][2]); acc[0][3] = fmaf(a0, b3, acc[0][3]);
            acc[1][0] = fmaf(a1, b0, acc[1][0]); acc[1][1] = fmaf(a1, b1, acc[1][1]);
            acc[1][2] = fmaf(a1, b2, acc[1][2]); acc[1][3] = fmaf(a1, b3, acc[1][3]);
            acc[2][0] = fmaf(a2, b0, acc[2][0]); acc[2][1] = fmaf(a2, b1, acc[2][1]);
            acc[2][2] = fmaf(a2, b2, acc[2][2]); acc[2][3] = fmaf(a2, b3, acc[2][3]);
            acc[3][0] = fmaf(a3, b0, acc[3][0]); acc[3][1] = fmaf(a3, b1, acc[3][1]);
            acc[3][2] = fmaf(a3, b2, acc[3][2]); acc[3][3] = fmaf(a3, b3, acc[3][3]);
        }
        __syncthreads();
    }

#pragma unroll
    for (int i = 0; i < 4; i++) {
        int mm = bm + ty * 4 + i;
        float* cptr;
        if (SCATTER_OUT) cptr = C + (long)rowbase[mm];
        else             cptr = C + (long)mm * N;
        int nn = bn + tx * 4;
        cptr[nn + 0] = acc[i][0];
        cptr[nn + 1] = acc[i][1];
        cptr[nn + 2] = acc[i][2];
        cptr[nn + 3] = acc[i][3];
    }
}

// ---------------------------------------------------------------------------
// Attention: one block per (window, head). 512 threads = 16 warps.
// smem: Ks/Vs padded to 36 floats/row, Qs 32/row, bias column, mask, column
// codes, and per-warp probability rows (padded to 296 for 16B alignment).
// ---------------------------------------------------------------------------
#define SM_K    0
#define SM_V    (NTOK * KPAD)                  // 10584
#define SM_Q    (SM_V + NTOK * KPAD)           // 21168
#define SM_BIAS (SM_Q + NTOK * DH)             // 30576
#define SM_MSK  (SM_BIAS + NBIAS)              // 32435
#define SM_CC   (SM_MSK + NTOK)                // 32729 (ints)
#define SM_P    33024                          // multiple of 4 floats (16B aligned)
#define SM_TOT  (SM_P + 16 * PROW_PAD)         // 37760 floats = 151040 B

__global__ void __launch_bounds__(512)
attn_kernel(const float* __restrict__ qkv, const int* __restrict__ mask,
            const float* __restrict__ bias_table, float* __restrict__ aout) {
    extern __shared__ float sm[];
    float* Ks    = sm + SM_K;
    float* Vs    = sm + SM_V;
    float* Qs    = sm + SM_Q;
    float* biasC = sm + SM_BIAS;
    float* msk   = sm + SM_MSK;
    int*   ccode = (int*)(sm + SM_CC);
    float* prow  = sm + SM_P;

    const int w = blockIdx.x;
    const int h = blockIdx.y;
    const int tid = threadIdx.x;
    const float scale = 0.17677669529663687f;  // 32^-0.5

    // Stage Q, K, V for this (window, head)
    const float* qbase = qkv + (long)w * NTOK * (3 * DIM) + h * DH;
    for (int idx = tid; idx < NTOK * DH; idx += 512) {
        int t = idx >> 5, d = idx & 31;
        long o = (long)t * (3 * DIM) + d;
        Qs[t * DH + d]   = qbase[o];
        Ks[t * KPAD + d] = qbase[o + DIM];
        Vs[t * KPAD + d] = qbase[o + 2 * DIM];
    }
    // Stage this head's bias column
    for (int i = tid; i < NBIAS; i += 512) biasC[i] = bias_table[i * HEADS + h];
    // Stage mask (column-wise) and per-token relative codes
    const int* mbase = mask + (long)w * NTOK;   // (w*49 + r)*6 + l, 49*6 = 294
    for (int j = tid; j < NTOK; j += 512) {
        int l = j / 49, r = j % 49;
        msk[j] = (float)mbase[r * AGENT + l];
        int w1 = r / 7, w2 = r % 7;
        ccode[j] = l * 169 + w1 * 13 + w2;
    }
    __syncthreads();

    const int warp = tid >> 5, lane = tid & 31;
    float* prw = prow + warp * PROW_PAD;

    for (int i = warp; i < NTOK; i += 16) {
        const int rc = ccode[i] + 929;          // 5*169 + 6*13 + 6
        const float4* q4 = (const float4*)(Qs + i * DH);

        float s[10];
#pragma unroll
        for (int jj = 0; jj < 10; jj++) {
            int j = lane + jj * 32;
            if (j < NTOK) {
                const float4* k4 = (const float4*)(Ks + j * KPAD);
                float acc = 0.f;
#pragma unroll
                for (int d = 0; d < 8; d++) {
                    float4 a = q4[d], c = k4[d];
                    acc = fmaf(a.x, c.x, acc);
                    acc = fmaf(a.y, c.y, acc);
                    acc = fmaf(a.z, c.z, acc);
                    acc = fmaf(a.w, c.w, acc);
                }
                float sv = fmaf(acc, scale, biasC[rc - ccode[j]]);
                s[jj] = (msk[j] == 0.f) ? -1e9f : sv;   // replace semantics (matches jnp.where)
            } else {
                s[jj] = -3.0e38f;
            }
        }
        // softmax over the row
        float mx = s[0];
#pragma unroll
        for (int jj = 1; jj < 10; jj++) mx = fmaxf(mx, s[jj]);
#pragma unroll
        for (int o = 16; o > 0; o >>= 1) mx = fmaxf(mx, __shfl_xor_sync(0xffffffffu, mx, o));
        float sum = 0.f;
#pragma unroll
        for (int jj = 0; jj < 10; jj++) {
            float e = __expf(s[jj] - mx);
            s[jj] = e;
            sum += e;
        }
#pragma unroll
        for (int o = 16; o > 0; o >>= 1) sum += __shfl_xor_sync(0xffffffffu, sum, o);
        float inv = 1.f / sum;
#pragma unroll
        for (int jj = 0; jj < 10; jj++) {
            int j = lane + jj * 32;
            if (j < NTOK) prw[j] = s[jj] * inv;
        }
        // pad tail so float4 AV loop reads zeros, not stale data
        if (lane < 2) prw[NTOK + lane] = 0.f;
        __syncwarp();

        // AV: out[i][lane] = sum_j p[j] * V[j][lane]
        float o = 0.f;
        int j = 0;
#pragma unroll 2
        for (; j + 4 <= NTOK; j += 4) {
            float4 p = *(const float4*)(prw + j);
            o = fmaf(p.x, Vs[(j + 0) * KPAD + lane], o);
            o = fmaf(p.y, Vs[(j + 1) * KPAD + lane], o);
            o = fmaf(p.z, Vs[(j + 2) * KPAD + lane], o);
            o = fmaf(p.w, Vs[(j + 3) * KPAD + lane], o);
        }
        for (; j < NTOK; j++) o = fmaf(prw[j], Vs[j * KPAD + lane], o);

        aout[((long)w * NTOK + i) * DIM + h * DH + lane] = o;
        __syncwarp();
    }
}

// ---------------------------------------------------------------------------
extern "C" void kernel_launch(void* const* d_in, const int* in_sizes, int n_in,
                              void* d_out, int out_size) {
    const float* x          = (const float*)d_in[0];
    const int*   mask       = (const int*)d_in[1];
    const float* w_qkv      = (const float*)d_in[2];
    const float* w_out      = (const float*)d_in[3];
    const float* bias_table = (const float*)d_in[4];
    float* out = (float*)d_out;

    void *rbp_, *qkvp_, *attp_;
    cudaGetSymbolAddress(&rbp_, g_rowbase);
    cudaGetSymbolAddress(&qkvp_, g_qkv);
    cudaGetSymbolAddress(&attp_, g_att);
    int*   rb   = (int*)rbp_;
    float* qkvb = (float*)qkvp_;
    float* attb = (float*)attp_;

    cudaFuncSetAttribute(attn_kernel, cudaFuncAttributeMaxDynamicSharedMemorySize,
                         SM_TOT * (int)sizeof(float));

    rowbase_kernel<<<(MROWS + 255) / 256, 256>>>(rb);

    // QKV projection: (37632 x 256) @ (768 x 256)^T -> (37632 x 768)
    {
        dim3 grid(3 * DIM / 64, MROWS / 64);
        gemm_kernel<1, 0><<<grid, 256>>>(x, rb, w_qkv, qkvb, 3 * DIM);
    }

    // Attention per (window, head)
    {
        dim3 grid(NWIN, HEADS);
        attn_kernel<<<grid, 512, SM_TOT * (int)sizeof(float)>>>(qkvb, mask, bias_table, attb);
    }

    // Output projection + scatter to (B, L, X, Y, W1, W2, C)
    {
        dim3 grid(DIM / 64, MROWS / 64);
        gemm_kernel<0, 1><<<grid, 256>>>(attb, rb, w_out, out, DIM);
    }
}

// round 3
// speedup vs baseline: 2.6004x; 2.6004x over previous
#include <cuda_runtime.h>
#include <cuda_bf16.h>

// Problem constants
#define BATCH   2
#define AGENT   6
#define XW      8
#define YW      8
#define WIN     7
#define DIM     256
#define HEADS   8
#define DH      32
#define NWIN    (BATCH * XW * YW)      // 128 windows
#define NTOK    (AGENT * WIN * WIN)    // 294 tokens per window
#define MROWS   (NWIN * NTOK)          // 37632
#define NBIAS   1859                   // (2*6-1)*(13)*(13)

#define KPAD 36                        // K/V smem row pad (16B-aligned rows)
#define PROW_PAD 296                   // per-row P pad: 296 floats = 1184 B (16B aligned)
#define NGROUP 74                      // ceil(294/4) row groups

__device__ int   g_rowbase[MROWS];
__device__ float g_qkv[(size_t)MROWS * 3 * DIM];   // ~115.6 MB
__device__ float g_att[(size_t)MROWS * DIM];       // ~38.5 MB

// ---------------------------------------------------------------------------
__global__ void rowbase_kernel(int* __restrict__ rb) {
    int m = blockIdx.x * 256 + threadIdx.x;
    if (m >= MROWS) return;
    int w = m / NTOK, t = m % NTOK;
    int b = w >> 6, xy = w & 63, x_ = xy >> 3, y_ = xy & 7;
    int l = t / 49, r = t % 49, w1 = r / 7, w2 = r % 7;
    rb[m] = ((((((b * AGENT + l) * XW + x_) * YW + y_) * WIN + w1) * WIN + w2)) * DIM;
}

// ---------------------------------------------------------------------------
// Tiled fp32 GEMM: C[m][n] = sum_k A[m][k] * W[n][k]   (K = 256 fixed)
// BM=BN=128, BK=16, 256 threads, 8x8 microtile (FMA:LDS-float = 4).
// ---------------------------------------------------------------------------
template <int GATHER_A, int SCATTER_OUT>
__global__ void __launch_bounds__(256)
gemm_kernel(const float* __restrict__ A, const int* __restrict__ rowbase,
            const float* __restrict__ W, float* __restrict__ C, int N) {
    __shared__ float As[16][132];
    __shared__ float Bs[16][132];

    int tid = threadIdx.x;
    int bm = blockIdx.y * 128;
    int bn = blockIdx.x * 128;

    int lr = tid >> 2;          // 0..63
    int lk = (tid & 3) * 4;     // 0,4,8,12

    long a0 = GATHER_A ? (long)rowbase[bm + lr]      : (long)(bm + lr) * DIM;
    long a1 = GATHER_A ? (long)rowbase[bm + lr + 64] : (long)(bm + lr + 64) * DIM;
    const float* ap0 = A + a0;
    const float* ap1 = A + a1;
    const float* bp0 = W + (long)(bn + lr) * DIM;
    const float* bp1 = W + (long)(bn + lr + 64) * DIM;

    int tx = tid & 15, ty = tid >> 4;
    float acc[8][8];
#pragma unroll
    for (int i = 0; i < 8; i++)
#pragma unroll
        for (int j = 0; j < 8; j++) acc[i][j] = 0.f;

    for (int k0 = 0; k0 < DIM; k0 += 16) {
        float4 av0 = *(const float4*)(ap0 + k0 + lk);
        float4 av1 = *(const float4*)(ap1 + k0 + lk);
        float4 bv0 = *(const float4*)(bp0 + k0 + lk);
        float4 bv1 = *(const float4*)(bp1 + k0 + lk);
        As[lk + 0][lr] = av0.x; As[lk + 1][lr] = av0.y;
        As[lk + 2][lr] = av0.z; As[lk + 3][lr] = av0.w;
        As[lk + 0][lr + 64] = av1.x; As[lk + 1][lr + 64] = av1.y;
        As[lk + 2][lr + 64] = av1.z; As[lk + 3][lr + 64] = av1.w;
        Bs[lk + 0][lr] = bv0.x; Bs[lk + 1][lr] = bv0.y;
        Bs[lk + 2][lr] = bv0.z; Bs[lk + 3][lr] = bv0.w;
        Bs[lk + 0][lr + 64] = bv1.x; Bs[lk + 1][lr + 64] = bv1.y;
        Bs[lk + 2][lr + 64] = bv1.z; Bs[lk + 3][lr + 64] = bv1.w;
        __syncthreads();
#pragma unroll
        for (int k = 0; k < 16; k++) {
            float4 aA = *(const float4*)&As[k][ty * 8];
            float4 aB = *(const float4*)&As[k][ty * 8 + 4];
            float4 bA = *(const float4*)&Bs[k][tx * 8];
            float4 bB = *(const float4*)&Bs[k][tx * 8 + 4];
            float ar[8] = {aA.x, aA.y, aA.z, aA.w, aB.x, aB.y, aB.z, aB.w};
            float br[8] = {bA.x, bA.y, bA.z, bA.w, bB.x, bB.y, bB.z, bB.w};
#pragma unroll
            for (int i = 0; i < 8; i++)
#pragma unroll
                for (int j = 0; j < 8; j++)
                    acc[i][j] = fmaf(ar[i], br[j], acc[i][j]);
        }
        __syncthreads();
    }

#pragma unroll
    for (int i = 0; i < 8; i++) {
        int mm = bm + ty * 8 + i;
        float* cptr;
        if (SCATTER_OUT) cptr = C + (long)rowbase[mm];
        else             cptr = C + (long)mm * N;
        int nn = bn + tx * 8;
        *(float4*)(cptr + nn)     = make_float4(acc[i][0], acc[i][1], acc[i][2], acc[i][3]);
        *(float4*)(cptr + nn + 4) = make_float4(acc[i][4], acc[i][5], acc[i][6], acc[i][7]);
    }
}

// ---------------------------------------------------------------------------
// Attention: one block per (window, head). 512 threads = 16 warps.
// Each warp processes 4 query rows per iteration: K rows & V rows are loaded
// from smem once per 4 rows (4x / 2.5x less crossbar traffic than 1 row/warp).
// ---------------------------------------------------------------------------
#define SM_K    0
#define SM_V    (NTOK * KPAD)                  // 10584
#define SM_Q    (SM_V + NTOK * KPAD)           // 21168
#define SM_BIAS (SM_Q + NTOK * DH)             // 30576
#define SM_MSK  (SM_BIAS + NBIAS)              // 32435
#define SM_CC   (SM_MSK + NTOK)                // 32729 (ints)
#define SM_P    33024                          // 16B aligned
#define SM_TOT  (SM_P + 64 * PROW_PAD)         // 51968 floats = 207,872 B

__global__ void __launch_bounds__(512)
attn_kernel(const float* __restrict__ qkv, const int* __restrict__ mask,
            const float* __restrict__ bias_table, float* __restrict__ aout) {
    extern __shared__ float sm[];
    float* Ks    = sm + SM_K;
    float* Vs    = sm + SM_V;
    float* Qs    = sm + SM_Q;
    float* biasC = sm + SM_BIAS;
    float* msk   = sm + SM_MSK;
    int*   ccode = (int*)(sm + SM_CC);
    float* prow  = sm + SM_P;

    const int w = blockIdx.x;
    const int h = blockIdx.y;
    const int tid = threadIdx.x;
    const float scale = 0.17677669529663687f;  // 32^-0.5

    // Stage Q, K, V for this (window, head)
    const float* qbase = qkv + (long)w * NTOK * (3 * DIM) + h * DH;
    for (int idx = tid; idx < NTOK * DH; idx += 512) {
        int t = idx >> 5, d = idx & 31;
        long o = (long)t * (3 * DIM) + d;
        Qs[t * DH + d]   = qbase[o];
        Ks[t * KPAD + d] = qbase[o + DIM];
        Vs[t * KPAD + d] = qbase[o + 2 * DIM];
    }
    for (int i = tid; i < NBIAS; i += 512) biasC[i] = bias_table[i * HEADS + h];
    const int* mbase = mask + (long)w * NTOK;
    for (int j = tid; j < NTOK; j += 512) {
        int l = j / 49, r = j % 49;
        msk[j] = (float)mbase[r * AGENT + l];
        int w1 = r / 7, w2 = r % 7;
        ccode[j] = l * 169 + w1 * 13 + w2;
    }
    __syncthreads();

    const int warp = tid >> 5, lane = tid & 31;

    for (int g = warp; g < NGROUP; g += 16) {
        const int i0 = g * 4;
        const int nrows = (NTOK - i0 < 4) ? (NTOK - i0) : 4;

        int rc[4];
#pragma unroll
        for (int r = 0; r < 4; r++) {
            int ir = i0 + r; if (ir >= NTOK) ir = NTOK - 1;
            rc[r] = ccode[ir] + 929;          // 5*169 + 6*13 + 6
        }

        float s[4][10];
#pragma unroll
        for (int jj = 0; jj < 10; jj++) {
            int j = lane + jj * 32;
            bool jv = (j < NTOK);
            int jc = jv ? j : 0;
            const float4* k4 = (const float4*)(Ks + jc * KPAD);
            float4 kr[8];
#pragma unroll
            for (int d = 0; d < 8; d++) kr[d] = k4[d];
            int   ccj = ccode[jc];
            float mj  = msk[jc];
#pragma unroll
            for (int r = 0; r < 4; r++) {
                int ir = i0 + r; if (ir >= NTOK) ir = NTOK - 1;
                const float4* q4 = (const float4*)(Qs + ir * DH);
                float acc = 0.f;
#pragma unroll
                for (int d = 0; d < 8; d++) {
                    float4 a = q4[d], c = kr[d];
                    acc = fmaf(a.x, c.x, acc);
                    acc = fmaf(a.y, c.y, acc);
                    acc = fmaf(a.z, c.z, acc);
                    acc = fmaf(a.w, c.w, acc);
                }
                float sv = fmaf(acc, scale, biasC[rc[r] - ccj]);
                sv = (mj == 0.f) ? -1e9f : sv;     // replace semantics (jnp.where)
                s[r][jj] = jv ? sv : -3.0e38f;
            }
        }

        // Softmax per row; write normalized P rows to smem
#pragma unroll
        for (int r = 0; r < 4; r++) {
            float mx = s[r][0];
#pragma unroll
            for (int jj = 1; jj < 10; jj++) mx = fmaxf(mx, s[r][jj]);
#pragma unroll
            for (int o = 16; o > 0; o >>= 1) mx = fmaxf(mx, __shfl_xor_sync(0xffffffffu, mx, o));
            float sum = 0.f;
#pragma unroll
            for (int jj = 0; jj < 10; jj++) {
                float e = __expf(s[r][jj] - mx);
                s[r][jj] = e;
                sum += e;
            }
#pragma unroll
            for (int o = 16; o > 0; o >>= 1) sum += __shfl_xor_sync(0xffffffffu, sum, o);
            float inv = 1.f / sum;
            float* prw = prow + (warp * 4 + r) * PROW_PAD;
#pragma unroll
            for (int jj = 0; jj < 10; jj++) {
                int j = lane + jj * 32;
                if (j < NTOK) prw[j] = s[r][jj] * inv;
            }
            if (lane < 2) prw[NTOK + lane] = 0.f;   // zero pad for float4 AV loop
        }
        __syncwarp();

        // AV: o[r][lane] = sum_j p_r[j] * V[j][lane]; V loaded once per 4 rows
        const float* p0 = prow + (warp * 4 + 0) * PROW_PAD;
        const float* p1 = prow + (warp * 4 + 1) * PROW_PAD;
        const float* p2 = prow + (warp * 4 + 2) * PROW_PAD;
        const float* p3 = prow + (warp * 4 + 3) * PROW_PAD;
        float o0 = 0.f, o1 = 0.f, o2 = 0.f, o3 = 0.f;
#pragma unroll 2
        for (int j = 0; j < NTOK; j += 4) {
            float4 a = *(const float4*)(p0 + j);
            float4 b = *(const float4*)(p1 + j);
            float4 c = *(const float4*)(p2 + j);
            float4 d = *(const float4*)(p3 + j);
            float v0 = Vs[(j + 0) * KPAD + lane];
            float v1 = Vs[(j + 1) * KPAD + lane];
            float v2 = Vs[(j + 2) * KPAD + lane];
            float v3 = Vs[(j + 3) * KPAD + lane];
            o0 = fmaf(a.x, v0, o0); o0 = fmaf(a.y, v1, o0); o0 = fmaf(a.z, v2, o0); o0 = fmaf(a.w, v3, o0);
            o1 = fmaf(b.x, v0, o1); o1 = fmaf(b.y, v1, o1); o1 = fmaf(b.z, v2, o1); o1 = fmaf(b.w, v3, o1);
            o2 = fmaf(c.x, v0, o2); o2 = fmaf(c.y, v1, o2); o2 = fmaf(c.z, v2, o2); o2 = fmaf(c.w, v3, o2);
            o3 = fmaf(d.x, v0, o3); o3 = fmaf(d.y, v1, o3); o3 = fmaf(d.z, v2, o3); o3 = fmaf(d.w, v3, o3);
        }
        // Note: j=292 chunk reads p[294..295]=0; V rows 294/295 read staged Q
        // floats (finite), multiplied by exactly 0 -> no contribution.

        float ov[4] = {o0, o1, o2, o3};
#pragma unroll
        for (int r = 0; r < 4; r++) {
            if (r < nrows)
                aout[((long)w * NTOK + (i0 + r)) * DIM + h * DH + lane] = ov[r];
        }
        __syncwarp();
    }
}

// ---------------------------------------------------------------------------
extern "C" void kernel_launch(void* const* d_in, const int* in_sizes, int n_in,
                              void* d_out, int out_size) {
    const float* x          = (const float*)d_in[0];
    const int*   mask       = (const int*)d_in[1];
    const float* w_qkv      = (const float*)d_in[2];
    const float* w_out      = (const float*)d_in[3];
    const float* bias_table = (const float*)d_in[4];
    float* out = (float*)d_out;

    void *rbp_, *qkvp_, *attp_;
    cudaGetSymbolAddress(&rbp_, g_rowbase);
    cudaGetSymbolAddress(&qkvp_, g_qkv);
    cudaGetSymbolAddress(&attp_, g_att);
    int*   rb   = (int*)rbp_;
    float* qkvb = (float*)qkvp_;
    float* attb = (float*)attp_;

    cudaFuncSetAttribute(attn_kernel, cudaFuncAttributeMaxDynamicSharedMemorySize,
                         SM_TOT * (int)sizeof(float));

    rowbase_kernel<<<(MROWS + 255) / 256, 256>>>(rb);

    // QKV projection: (37632 x 256) @ (768 x 256)^T -> (37632 x 768)
    {
        dim3 grid(3 * DIM / 128, MROWS / 128);
        gemm_kernel<1, 0><<<grid, 256>>>(x, rb, w_qkv, qkvb, 3 * DIM);
    }

    // Attention per (window, head)
    {
        dim3 grid(NWIN, HEADS);
        attn_kernel<<<grid, 512, SM_TOT * (int)sizeof(float)>>>(qkvb, mask, bias_table, attb);
    }

    // Output projection + scatter to (B, L, X, Y, W1, W2, C)
    {
        dim3 grid(DIM / 128, MROWS / 128);
        gemm_kernel<0, 1><<<grid, 256>>>(attb, rb, w_out, out, DIM);
    }
}